// round 10
// baseline (speedup 1.0000x reference)
#include <cuda_runtime.h>
#include <cuda_fp16.h>
#include <cstdint>

#define LAT   2048
#define MAXB  4096
#define K1PAD 2112            // n_freq (2074) padded to multiple of 64

// ---------------------------------------------------------------------------
// Scratch (static __device__ — no allocations allowed)
// ---------------------------------------------------------------------------
__device__ __half g_Wt[(size_t)LAT * K1PAD];   // W^T, K-major (K = n_freq)
__device__ __half g_Ct[(size_t)LAT * K1PAD];   // C^T, K-major
__device__ __half g_Mt[(size_t)LAT * LAT];     // M^T rows n, K-major over m
__device__ __half g_x [(size_t)MAXB * LAT];    // x, fp16
__device__ unsigned g_max_bits;

// ---------------------------------------------------------------------------
// Helpers
// ---------------------------------------------------------------------------
__device__ __forceinline__ unsigned fenc(float f) {
    unsigned u = __float_as_uint(f);
    return (u & 0x80000000u) ? ~u : (u | 0x80000000u);
}
__device__ __forceinline__ float fdec(unsigned u) {
    unsigned b = (u & 0x80000000u) ? (u ^ 0x80000000u) : ~u;
    return __uint_as_float(b);
}
__device__ __forceinline__ uint32_t smem_u32(const void* p) {
    return (uint32_t)__cvta_generic_to_shared(p);
}
__device__ __forceinline__ void cpasync16(uint32_t dst, const void* src) {
    asm volatile("cp.async.cg.shared.global [%0], [%1], 16;" :: "r"(dst), "l"(src));
}
#define CP_COMMIT() asm volatile("cp.async.commit_group;" ::: "memory")
#define CP_WAIT5()  asm volatile("cp.async.wait_group 5;" ::: "memory")

__device__ __forceinline__ void ldsm4(uint32_t* r, uint32_t addr) {
    asm volatile("ldmatrix.sync.aligned.m8n8.x4.shared.b16 {%0,%1,%2,%3}, [%4];"
                 : "=r"(r[0]), "=r"(r[1]), "=r"(r[2]), "=r"(r[3]) : "r"(addr));
}
__device__ __forceinline__ void mma16816(float* c, const uint32_t* a, const uint32_t* b) {
    asm volatile("mma.sync.aligned.m16n8k16.row.col.f32.f16.f16.f32 "
                 "{%0,%1,%2,%3}, {%4,%5,%6,%7}, {%8,%9}, {%0,%1,%2,%3};"
                 : "+f"(c[0]), "+f"(c[1]), "+f"(c[2]), "+f"(c[3])
                 : "r"(a[0]), "r"(a[1]), "r"(a[2]), "r"(a[3]), "r"(b[0]), "r"(b[1]));
}

// smem tile geometry: 64 rows x 64 fp16 (128B) padded to 144B (9*16B — conflict-free)
#define ROWB        144
#define TILE_B      (64 * ROWB)       // 9216
#define STAGE_B     (2 * TILE_B)      // 18432 (A, B)
#define NSTAGE      7
#define SMEM_BYTES  (NSTAGE * STAGE_B)   // 129024 -> forces occ=1 (slots = 148)

// ---------------------------------------------------------------------------
// Prep kernels
// ---------------------------------------------------------------------------
// transpose to fp16: src [K][2048] f32 -> dst [2048][K1PAD] half (pad = 0)
__global__ void transpose_half_kernel(const float* __restrict__ src, int K, int which)
{
    __shared__ float t[32][33];
    if (which == 0 && blockIdx.x == 0 && blockIdx.y == 0 &&
        threadIdx.x == 0 && threadIdx.y == 0)
        g_max_bits = 0u;                      // folded reset (deterministic)
    __half* dst = which ? g_Ct : g_Wt;
    const int kb = blockIdx.y * 32;
    const int mb = blockIdx.x * 32;
    const int tx = threadIdx.x, ty = threadIdx.y;
#pragma unroll
    for (int r = ty; r < 32; r += 8) {
        const int k = kb + r;
        t[r][tx] = (k < K) ? src[(size_t)k * LAT + mb + tx] : 0.f;
    }
    __syncthreads();
#pragma unroll
    for (int r = ty; r < 32; r += 8)
        dst[(size_t)(mb + r) * K1PAD + kb + tx] = __float2half_rn(t[tx][r]);
}

__global__ void x_half_kernel(const float* __restrict__ x, int n2)
{
    const int i = blockIdx.x * blockDim.x + threadIdx.x;
    if (i < n2) {
        const float2 v = ((const float2*)x)[i];
        ((__half2*)g_x)[i] = __floats2half2_rn(v.x, v.y);
    }
}

// ---------------------------------------------------------------------------
// GEMM mainloop: 64x64 CTA tile, 128 threads (4 warps as 2m x 2n, warp 32x32),
// K-chunks of 64 (4 k16-steps), 7-stage cp.async pipeline.
// acc[mt][nj][4]: mt in 0..1 (m16), nj in 0..3 (n8).
// ---------------------------------------------------------------------------
__device__ __forceinline__ void gemm_main(
    const __half* __restrict__ A, const __half* __restrict__ B,
    int arow0, int brow0, int ldk, int nchunks,
    char* smem, float acc[2][4][4])
{
    const int tid = threadIdx.x;
    const int lane = tid & 31;
    const int w = tid >> 5;
    const int wm = w >> 1;            // 0..1
    const int wn = w & 1;             // 0..1
    const uint32_t sbase = smem_u32(smem);

#pragma unroll
    for (int mt = 0; mt < 2; mt++)
#pragma unroll
        for (int nj = 0; nj < 4; nj++)
#pragma unroll
            for (int q = 0; q < 4; q++) acc[mt][nj][q] = 0.f;

    // loader: one thread per row; threads 0..63 -> A rows, 64..127 -> B rows.
    const int lr = tid & 63;
    const int lt = tid >> 6;
    const __half* grow = lt ? (B + (size_t)(brow0 + lr) * ldk)
                            : (A + (size_t)(arow0 + lr) * ldk);
    const uint32_t sdst0 = sbase + lt * TILE_B + lr * ROWB;

    // ldmatrix lane offsets (within a stage)
    uint32_t aoff[4][2], boff[4][2];
#pragma unroll
    for (int ks = 0; ks < 4; ks++) {
#pragma unroll
        for (int mt = 0; mt < 2; mt++)
            aoff[ks][mt] = sbase + (uint32_t)((wm * 32 + mt * 16 + (lane & 15)) * ROWB
                                              + ks * 32 + (lane >> 4) * 16);
#pragma unroll
        for (int nt = 0; nt < 2; nt++)
            boff[ks][nt] = sbase + (uint32_t)(TILE_B
                              + (wn * 32 + nt * 16 + (lane & 7) + (lane >> 4) * 8) * ROWB
                              + ks * 32 + ((lane >> 3) & 1) * 16);
    }

#define LOAD_STAGE(c, s)                                                       \
    do {                                                                       \
        const char* p = (const char*)(grow + (size_t)(c) * 64);                \
        const uint32_t d = sdst0 + (uint32_t)(s) * STAGE_B;                    \
        _Pragma("unroll")                                                      \
        for (int j = 0; j < 8; j++) cpasync16(d + j * 16, p + j * 16);         \
    } while (0)

#pragma unroll
    for (int c = 0; c < NSTAGE - 1; c++) { LOAD_STAGE(c, c); CP_COMMIT(); }

    int s = 0, ps = NSTAGE - 1;
    for (int c = 0; c < nchunks; ++c) {
        CP_WAIT5();
        __syncthreads();
        if (c + NSTAGE - 1 < nchunks) LOAD_STAGE(c + NSTAGE - 1, ps);
        CP_COMMIT();

        const uint32_t so = (uint32_t)s * STAGE_B;
        uint32_t a[4][2][4], b[4][2][4];
#pragma unroll
        for (int ks = 0; ks < 4; ks++) {
            ldsm4(a[ks][0], aoff[ks][0] + so);
            ldsm4(a[ks][1], aoff[ks][1] + so);
            ldsm4(b[ks][0], boff[ks][0] + so);
            ldsm4(b[ks][1], boff[ks][1] + so);
        }
#pragma unroll
        for (int ks = 0; ks < 4; ks++)
#pragma unroll
            for (int mt = 0; mt < 2; mt++)
#pragma unroll
                for (int nt = 0; nt < 2; nt++) {
                    mma16816(acc[mt][nt * 2 + 0], a[ks][mt], &b[ks][nt][0]);
                    mma16816(acc[mt][nt * 2 + 1], a[ks][mt], &b[ks][nt][2]);
                }
        if (++s == NSTAGE) s = 0;
        if (++ps == NSTAGE) ps = 0;
    }
#undef LOAD_STAGE
}

// ---------------------------------------------------------------------------
// GEMM1: Mt[n][m] = sum_k Ct[n][k] * Wt[m][k]; epilogue rounds to fp16.
// ---------------------------------------------------------------------------
__global__ __launch_bounds__(128, 1) void gemm1_tc()
{
    extern __shared__ __align__(128) char smem[];
    float acc[2][4][4];
    gemm_main(g_Ct, g_Wt, blockIdx.y * 64, blockIdx.x * 64, K1PAD, K1PAD / 64,
              smem, acc);

    const int lane = threadIdx.x & 31;
    const int w = threadIdx.x >> 5;
    const int r0 = blockIdx.y * 64 + (w >> 1) * 32;
    const int c0 = blockIdx.x * 64 + (w & 1) * 32;

#pragma unroll
    for (int mt = 0; mt < 2; mt++) {
#pragma unroll
        for (int nj = 0; nj < 4; nj++) {
            const int col = c0 + nj * 8 + (lane & 3) * 2;
            const float* cc = acc[mt][nj];
#pragma unroll
            for (int h = 0; h < 2; h++) {
                const int r = r0 + mt * 16 + (lane >> 2) + h * 8;
                *(__half2*)(g_Mt + (size_t)r * LAT + col) =
                    __floats2half2_rn(cc[2 * h + 0], cc[2 * h + 1]);
            }
        }
    }
}

// ---------------------------------------------------------------------------
// GEMM2: out[b][n] = sum_m x[b][m] * Mt[n][m]; fused global max.
// ---------------------------------------------------------------------------
__global__ __launch_bounds__(128, 1) void gemm2_tc(float* __restrict__ out)
{
    extern __shared__ __align__(128) char smem[];
    float acc[2][4][4];
    gemm_main(g_x, g_Mt, blockIdx.y * 64, blockIdx.x * 64, LAT, LAT / 64,
              smem, acc);

    const int lane = threadIdx.x & 31;
    const int w = threadIdx.x >> 5;
    const int r0 = blockIdx.y * 64 + (w >> 1) * 32;
    const int c0 = blockIdx.x * 64 + (w & 1) * 32;

    float lmax = -3.402823466e+38f;
#pragma unroll
    for (int mt = 0; mt < 2; mt++) {
#pragma unroll
        for (int nj = 0; nj < 4; nj++) {
            const int col = c0 + nj * 8 + (lane & 3) * 2;
            const float* cc = acc[mt][nj];
#pragma unroll
            for (int h = 0; h < 2; h++) {
                const int r = r0 + mt * 16 + (lane >> 2) + h * 8;
                float2 v = make_float2(cc[2 * h + 0], cc[2 * h + 1]);
                lmax = fmaxf(lmax, fmaxf(v.x, v.y));
                *(float2*)(out + (size_t)r * LAT + col) = v;
            }
        }
    }

#pragma unroll
    for (int o = 16; o > 0; o >>= 1)
        lmax = fmaxf(lmax, __shfl_xor_sync(0xFFFFFFFFu, lmax, o));
    __shared__ float wmax[4];
    if (lane == 0) wmax[w] = lmax;
    __syncthreads();
    if (threadIdx.x == 0) {
        const float m = fmaxf(fmaxf(wmax[0], wmax[1]), fmaxf(wmax[2], wmax[3]));
        atomicMax(&g_max_bits, fenc(m));
    }
}

// ---------------------------------------------------------------------------
// out *= 1/max
// ---------------------------------------------------------------------------
__global__ void scale_kernel(float* __restrict__ out, int n4)
{
    const float inv = 1.0f / fdec(g_max_bits);
    const int i = blockIdx.x * blockDim.x + threadIdx.x;
    if (i < n4) {
        float4 v = ((float4*)out)[i];
        v.x *= inv; v.y *= inv; v.z *= inv; v.w *= inv;
        ((float4*)out)[i] = v;
    }
}

// ---------------------------------------------------------------------------
extern "C" void kernel_launch(void* const* d_in, const int* in_sizes, int n_in,
                              void* d_out, int out_size)
{
    const float* x = (const float*)d_in[0];   // (B, 2048)
    const float* W = (const float*)d_in[1];   // (NF, 2048)
    const float* C = (const float*)d_in[2];   // (NF, 2048)
    float* out = (float*)d_out;

    const int B  = in_sizes[0] / LAT;         // 4096
    const int NF = in_sizes[1] / LAT;         // 2074

    cudaFuncSetAttribute(gemm1_tc, cudaFuncAttributeMaxDynamicSharedMemorySize, SMEM_BYTES);
    cudaFuncSetAttribute(gemm2_tc, cudaFuncAttributeMaxDynamicSharedMemorySize, SMEM_BYTES);

    dim3 tb(32, 8);
    transpose_half_kernel<<<dim3(LAT / 32, K1PAD / 32), tb>>>(W, NF, 0);
    transpose_half_kernel<<<dim3(LAT / 32, K1PAD / 32), tb>>>(C, NF, 1);
    const int n2 = B * LAT / 2;
    x_half_kernel<<<(n2 + 255) / 256, 256>>>(x, n2);

    // GEMM1: Mt = (W^T C)^T   (2048x2048, K = K1PAD) — grid 1024 = 6.92 waves
    gemm1_tc<<<dim3(LAT / 64, LAT / 64), 128, SMEM_BYTES>>>();

    // GEMM2: out = x @ M + fused global max — grid 2048 = 13.84 waves
    gemm2_tc<<<dim3(LAT / 64, B / 64), 128, SMEM_BYTES>>>(out);

    const int n4 = out_size / 4;
    scale_kernel<<<(n4 + 255) / 256, 256>>>(out, n4);
}

// round 11
// speedup vs baseline: 1.4566x; 1.4566x over previous
#include <cuda_runtime.h>
#include <cuda_fp16.h>
#include <cstdint>

#define LAT   2048
#define MAXB  4096
#define K1PAD 2112            // n_freq (2074) padded to multiple of 64

// ---------------------------------------------------------------------------
// Scratch (static __device__ — no allocations allowed)
// ---------------------------------------------------------------------------
__device__ __half g_Wt[(size_t)LAT * K1PAD];   // W^T, K-major (K = n_freq)
__device__ __half g_Ct[(size_t)LAT * K1PAD];   // C^T, K-major
__device__ __half g_Mt[(size_t)LAT * LAT];     // M^T rows n, K-major over m
__device__ __half g_x [(size_t)MAXB * LAT];    // x, fp16
__device__ unsigned g_max_bits;

// ---------------------------------------------------------------------------
// Helpers
// ---------------------------------------------------------------------------
__device__ __forceinline__ unsigned fenc(float f) {
    unsigned u = __float_as_uint(f);
    return (u & 0x80000000u) ? ~u : (u | 0x80000000u);
}
__device__ __forceinline__ float fdec(unsigned u) {
    unsigned b = (u & 0x80000000u) ? (u ^ 0x80000000u) : ~u;
    return __uint_as_float(b);
}
__device__ __forceinline__ uint32_t smem_u32(const void* p) {
    return (uint32_t)__cvta_generic_to_shared(p);
}
__device__ __forceinline__ void cpasync16(uint32_t dst, const void* src) {
    asm volatile("cp.async.cg.shared.global [%0], [%1], 16;" :: "r"(dst), "l"(src));
}
#define CP_COMMIT() asm volatile("cp.async.commit_group;" ::: "memory")
#define CP_WAIT4()  asm volatile("cp.async.wait_group 4;" ::: "memory")

__device__ __forceinline__ void ldsm4(uint32_t* r, uint32_t addr) {
    asm volatile("ldmatrix.sync.aligned.m8n8.x4.shared.b16 {%0,%1,%2,%3}, [%4];"
                 : "=r"(r[0]), "=r"(r[1]), "=r"(r[2]), "=r"(r[3]) : "r"(addr));
}
__device__ __forceinline__ void mma16816(float* c, const uint32_t* a, const uint32_t* b) {
    asm volatile("mma.sync.aligned.m16n8k16.row.col.f32.f16.f16.f32 "
                 "{%0,%1,%2,%3}, {%4,%5,%6,%7}, {%8,%9}, {%0,%1,%2,%3};"
                 : "+f"(c[0]), "+f"(c[1]), "+f"(c[2]), "+f"(c[3])
                 : "r"(a[0]), "r"(a[1]), "r"(a[2]), "r"(a[3]), "r"(b[0]), "r"(b[1]));
}

// smem tile geometry: rows x 64 fp16 (128B) padded to 144B (9*16B, conflict-free
// for ldmatrix: row stride = 36 words -> bank shift 4/row, distinct over 8 rows)
#define ROWB        144
#define TILE_A      (128 * ROWB)      // 18432 (A: 128 rows)
#define TILE_BB     (64 * ROWB)       // 9216  (B: 64 rows)
#define STAGE_B     (TILE_A + TILE_BB)   // 27648
#define NSTAGE      6
#define SMEM_BYTES  (NSTAGE * STAGE_B)   // 165888

// ---------------------------------------------------------------------------
// Prep kernels
// ---------------------------------------------------------------------------
// transpose to fp16: src [K][2048] f32 -> dst [2048][K1PAD] half (pad = 0)
__global__ void transpose_half_kernel(const float* __restrict__ src, int K, int which)
{
    __shared__ float t[32][33];
    if (which == 0 && blockIdx.x == 0 && blockIdx.y == 0 &&
        threadIdx.x == 0 && threadIdx.y == 0)
        g_max_bits = 0u;                      // folded reset (deterministic)
    __half* dst = which ? g_Ct : g_Wt;
    const int kb = blockIdx.y * 32;
    const int mb = blockIdx.x * 32;
    const int tx = threadIdx.x, ty = threadIdx.y;
#pragma unroll
    for (int r = ty; r < 32; r += 8) {
        const int k = kb + r;
        t[r][tx] = (k < K) ? src[(size_t)k * LAT + mb + tx] : 0.f;
    }
    __syncthreads();
#pragma unroll
    for (int r = ty; r < 32; r += 8)
        dst[(size_t)(mb + r) * K1PAD + kb + tx] = __float2half_rn(t[tx][r]);
}

__global__ void x_half_kernel(const float* __restrict__ x, int n2)
{
    const int i = blockIdx.x * blockDim.x + threadIdx.x;
    if (i < n2) {
        const float2 v = ((const float2*)x)[i];
        ((__half2*)g_x)[i] = __floats2half2_rn(v.x, v.y);
    }
}

// ---------------------------------------------------------------------------
// GEMM mainloop: 128(m) x 64(n) CTA tile, 256 threads = 8 warps (4m x 2n,
// warp tile 32x32), K-chunks of 64 (4 k16-steps), 6-stage cp.async pipeline.
// acc[mt][nj][4]: mt in 0..1 (m16), nj in 0..3 (n8).
// ---------------------------------------------------------------------------
__device__ __forceinline__ void gemm_main(
    const __half* __restrict__ A, const __half* __restrict__ B,
    int arow0, int brow0, int ldk, int nchunks,
    char* smem, float acc[2][4][4])
{
    const int tid = threadIdx.x;
    const int lane = tid & 31;
    const int w = tid >> 5;
    const int wm = w >> 1;            // 0..3 (m offset 32 each)
    const int wn = w & 1;             // 0..1 (n offset 32)
    const uint32_t sbase = smem_u32(smem);

#pragma unroll
    for (int mt = 0; mt < 2; mt++)
#pragma unroll
        for (int nj = 0; nj < 4; nj++)
#pragma unroll
            for (int q = 0; q < 4; q++) acc[mt][nj][q] = 0.f;

    // loaders: A: 2 threads/row x 128 rows (64B each = 4 cp16)
    //          B: 4 threads/row x 64 rows  (32B each = 2 cp16)
    const int ar = tid >> 1;              // 0..127
    const int ac = (tid & 1) * 64;        // byte offset in row
    const int br = tid >> 2;              // 0..63
    const int bc = (tid & 3) * 32;
    const __half* gA = A + (size_t)(arow0 + ar) * ldk + (ac >> 1);
    const __half* gB = B + (size_t)(brow0 + br) * ldk + (bc >> 1);
    const uint32_t adst = sbase + ar * ROWB + ac;
    const uint32_t bdst = sbase + TILE_A + br * ROWB + bc;

    // ldmatrix lane offsets (within a stage)
    uint32_t aoff[4][2], boff[4][2];
#pragma unroll
    for (int ks = 0; ks < 4; ks++) {
#pragma unroll
        for (int mt = 0; mt < 2; mt++)
            aoff[ks][mt] = sbase + (uint32_t)((wm * 32 + mt * 16 + (lane & 15)) * ROWB
                                              + ks * 32 + (lane >> 4) * 16);
#pragma unroll
        for (int nt = 0; nt < 2; nt++)
            boff[ks][nt] = sbase + (uint32_t)(TILE_A
                              + (wn * 32 + nt * 16 + (lane & 7) + (lane >> 4) * 8) * ROWB
                              + ks * 32 + ((lane >> 3) & 1) * 16);
    }

#define LOAD_STAGE(c, s)                                                       \
    do {                                                                       \
        const char* pa = (const char*)(gA + (size_t)(c) * 64);                 \
        const char* pb = (const char*)(gB + (size_t)(c) * 64);                 \
        const uint32_t so_ = (uint32_t)(s) * STAGE_B;                          \
        cpasync16(adst + so_,      pa);        cpasync16(adst + so_ + 16, pa + 16); \
        cpasync16(adst + so_ + 32, pa + 32);   cpasync16(adst + so_ + 48, pa + 48); \
        cpasync16(bdst + so_,      pb);        cpasync16(bdst + so_ + 16, pb + 16); \
    } while (0)

#pragma unroll
    for (int c = 0; c < NSTAGE - 1; c++) { LOAD_STAGE(c, c); CP_COMMIT(); }

    int s = 0, ps = NSTAGE - 1;
    for (int c = 0; c < nchunks; ++c) {
        CP_WAIT4();
        __syncthreads();
        if (c + NSTAGE - 1 < nchunks) LOAD_STAGE(c + NSTAGE - 1, ps);
        CP_COMMIT();

        const uint32_t so = (uint32_t)s * STAGE_B;
        uint32_t a[4][2][4], b[4][2][4];
#pragma unroll
        for (int ks = 0; ks < 4; ks++) {
            ldsm4(a[ks][0], aoff[ks][0] + so);
            ldsm4(a[ks][1], aoff[ks][1] + so);
            ldsm4(b[ks][0], boff[ks][0] + so);
            ldsm4(b[ks][1], boff[ks][1] + so);
        }
#pragma unroll
        for (int ks = 0; ks < 4; ks++)
#pragma unroll
            for (int mt = 0; mt < 2; mt++)
#pragma unroll
                for (int nt = 0; nt < 2; nt++) {
                    mma16816(acc[mt][nt * 2 + 0], a[ks][mt], &b[ks][nt][0]);
                    mma16816(acc[mt][nt * 2 + 1], a[ks][mt], &b[ks][nt][2]);
                }
        if (++s == NSTAGE) s = 0;
        if (++ps == NSTAGE) ps = 0;
    }
#undef LOAD_STAGE
}

// ---------------------------------------------------------------------------
// GEMM1: Mt[n][m] = sum_k Ct[n][k] * Wt[m][k]; epilogue rounds to fp16.
// A = Ct (128 n-rows), B = Wt (64 m-rows).
// ---------------------------------------------------------------------------
__global__ __launch_bounds__(256, 1) void gemm1_tc()
{
    extern __shared__ __align__(128) char smem[];
    float acc[2][4][4];
    gemm_main(g_Ct, g_Wt, blockIdx.y * 128, blockIdx.x * 64, K1PAD, K1PAD / 64,
              smem, acc);

    const int lane = threadIdx.x & 31;
    const int w = threadIdx.x >> 5;
    const int r0 = blockIdx.y * 128 + (w >> 1) * 32;
    const int c0 = blockIdx.x * 64 + (w & 1) * 32;

#pragma unroll
    for (int mt = 0; mt < 2; mt++) {
#pragma unroll
        for (int nj = 0; nj < 4; nj++) {
            const int col = c0 + nj * 8 + (lane & 3) * 2;
            const float* cc = acc[mt][nj];
#pragma unroll
            for (int h = 0; h < 2; h++) {
                const int r = r0 + mt * 16 + (lane >> 2) + h * 8;
                *(__half2*)(g_Mt + (size_t)r * LAT + col) =
                    __floats2half2_rn(cc[2 * h + 0], cc[2 * h + 1]);
            }
        }
    }
}

// ---------------------------------------------------------------------------
// GEMM2: out[b][n] = sum_m x[b][m] * Mt[n][m]; fused global max.
// A = x (128 batch rows), B = Mt (64 n-rows).
// ---------------------------------------------------------------------------
__global__ __launch_bounds__(256, 1) void gemm2_tc(float* __restrict__ out)
{
    extern __shared__ __align__(128) char smem[];
    float acc[2][4][4];
    gemm_main(g_x, g_Mt, blockIdx.y * 128, blockIdx.x * 64, LAT, LAT / 64,
              smem, acc);

    const int lane = threadIdx.x & 31;
    const int w = threadIdx.x >> 5;
    const int r0 = blockIdx.y * 128 + (w >> 1) * 32;
    const int c0 = blockIdx.x * 64 + (w & 1) * 32;

    float lmax = -3.402823466e+38f;
#pragma unroll
    for (int mt = 0; mt < 2; mt++) {
#pragma unroll
        for (int nj = 0; nj < 4; nj++) {
            const int col = c0 + nj * 8 + (lane & 3) * 2;
            const float* cc = acc[mt][nj];
#pragma unroll
            for (int h = 0; h < 2; h++) {
                const int r = r0 + mt * 16 + (lane >> 2) + h * 8;
                float2 v = make_float2(cc[2 * h + 0], cc[2 * h + 1]);
                lmax = fmaxf(lmax, fmaxf(v.x, v.y));
                *(float2*)(out + (size_t)r * LAT + col) = v;
            }
        }
    }

#pragma unroll
    for (int o = 16; o > 0; o >>= 1)
        lmax = fmaxf(lmax, __shfl_xor_sync(0xFFFFFFFFu, lmax, o));
    __shared__ float wmax[8];
    if (lane == 0) wmax[w] = lmax;
    __syncthreads();
    if (threadIdx.x == 0) {
        float m = wmax[0];
#pragma unroll
        for (int i = 1; i < 8; i++) m = fmaxf(m, wmax[i]);
        atomicMax(&g_max_bits, fenc(m));
    }
}

// ---------------------------------------------------------------------------
// out *= 1/max
// ---------------------------------------------------------------------------
__global__ void scale_kernel(float* __restrict__ out, int n4)
{
    const float inv = 1.0f / fdec(g_max_bits);
    const int i = blockIdx.x * blockDim.x + threadIdx.x;
    if (i < n4) {
        float4 v = ((float4*)out)[i];
        v.x *= inv; v.y *= inv; v.z *= inv; v.w *= inv;
        ((float4*)out)[i] = v;
    }
}

// ---------------------------------------------------------------------------
extern "C" void kernel_launch(void* const* d_in, const int* in_sizes, int n_in,
                              void* d_out, int out_size)
{
    const float* x = (const float*)d_in[0];   // (B, 2048)
    const float* W = (const float*)d_in[1];   // (NF, 2048)
    const float* C = (const float*)d_in[2];   // (NF, 2048)
    float* out = (float*)d_out;

    const int B  = in_sizes[0] / LAT;         // 4096
    const int NF = in_sizes[1] / LAT;         // 2074

    cudaFuncSetAttribute(gemm1_tc, cudaFuncAttributeMaxDynamicSharedMemorySize, SMEM_BYTES);
    cudaFuncSetAttribute(gemm2_tc, cudaFuncAttributeMaxDynamicSharedMemorySize, SMEM_BYTES);

    dim3 tb(32, 8);
    transpose_half_kernel<<<dim3(LAT / 32, K1PAD / 32), tb>>>(W, NF, 0);
    transpose_half_kernel<<<dim3(LAT / 32, K1PAD / 32), tb>>>(C, NF, 1);
    const int n2 = B * LAT / 2;
    x_half_kernel<<<(n2 + 255) / 256, 256>>>(x, n2);

    // GEMM1: Mt = (W^T C)^T — grid 32x16 = 512 CTAs (3.46 waves)
    gemm1_tc<<<dim3(LAT / 64, LAT / 128), 256, SMEM_BYTES>>>();

    // GEMM2: out = x @ M + fused global max — grid 32x32 = 1024 CTAs (6.92 waves)
    gemm2_tc<<<dim3(LAT / 64, B / 128), 256, SMEM_BYTES>>>(out);

    const int n4 = out_size / 4;
    scale_kernel<<<(n4 + 255) / 256, 256>>>(out, n4);
}

// round 12
// speedup vs baseline: 1.9534x; 1.3411x over previous
#include <cuda_runtime.h>
#include <cuda_fp16.h>
#include <cstdint>

#define LAT   2048
#define MAXB  4096
#define K1PAD 2112            // n_freq (2074) padded to multiple of 32

// ---------------------------------------------------------------------------
// Scratch (static __device__ — no allocations allowed)
// ---------------------------------------------------------------------------
__device__ __half g_Wt[(size_t)LAT * K1PAD];   // W^T, K-major (K = n_freq)
__device__ __half g_Ct[(size_t)LAT * K1PAD];   // C^T, K-major
__device__ __half g_Mt[(size_t)LAT * LAT];     // M^T rows n, K-major over m
__device__ __half g_x [(size_t)MAXB * LAT];    // x, fp16
__device__ unsigned g_max_bits;

// ---------------------------------------------------------------------------
// Helpers
// ---------------------------------------------------------------------------
__device__ __forceinline__ unsigned fenc(float f) {
    unsigned u = __float_as_uint(f);
    return (u & 0x80000000u) ? ~u : (u | 0x80000000u);
}
__device__ __forceinline__ float fdec(unsigned u) {
    unsigned b = (u & 0x80000000u) ? (u ^ 0x80000000u) : ~u;
    return __uint_as_float(b);
}
__device__ __forceinline__ uint32_t smem_u32(const void* p) {
    return (uint32_t)__cvta_generic_to_shared(p);
}
__device__ __forceinline__ void cpasync16(uint32_t dst, const void* src) {
    asm volatile("cp.async.cg.shared.global [%0], [%1], 16;" :: "r"(dst), "l"(src));
}
#define CP_COMMIT() asm volatile("cp.async.commit_group;" ::: "memory")
#define CP_WAIT3()  asm volatile("cp.async.wait_group 3;" ::: "memory")

__device__ __forceinline__ void ldsm4(uint32_t* r, uint32_t addr) {
    asm volatile("ldmatrix.sync.aligned.m8n8.x4.shared.b16 {%0,%1,%2,%3}, [%4];"
                 : "=r"(r[0]), "=r"(r[1]), "=r"(r[2]), "=r"(r[3]) : "r"(addr));
}
__device__ __forceinline__ void mma16816(float* c, const uint32_t* a, const uint32_t* b) {
    asm volatile("mma.sync.aligned.m16n8k16.row.col.f32.f16.f16.f32 "
                 "{%0,%1,%2,%3}, {%4,%5,%6,%7}, {%8,%9}, {%0,%1,%2,%3};"
                 : "+f"(c[0]), "+f"(c[1]), "+f"(c[2]), "+f"(c[3])
                 : "r"(a[0]), "r"(a[1]), "r"(a[2]), "r"(a[3]), "r"(b[0]), "r"(b[1]));
}

// smem tile geometry: 128 rows x 32 fp16 (64B) padded to 80B (conflict-free LDSM)
#define ROWB        80
#define TILE_B      (128 * ROWB)      // 10240
#define STAGE_B     (2 * TILE_B)      // 20480 (A, B)
#define NSTAGE      5
#define SMEM_BYTES  (NSTAGE * STAGE_B)   // 102400 -> occ=1

// ---------------------------------------------------------------------------
// Prep kernels
// ---------------------------------------------------------------------------
// transpose to fp16: src [K][2048] f32 -> dst [2048][K1PAD] half (pad = 0)
__global__ void transpose_half_kernel(const float* __restrict__ src, int K, int which)
{
    __shared__ float t[32][33];
    if (which == 0 && blockIdx.x == 0 && blockIdx.y == 0 &&
        threadIdx.x == 0 && threadIdx.y == 0)
        g_max_bits = 0u;                      // folded reset (deterministic)
    __half* dst = which ? g_Ct : g_Wt;
    const int kb = blockIdx.y * 32;
    const int mb = blockIdx.x * 32;
    const int tx = threadIdx.x, ty = threadIdx.y;
#pragma unroll
    for (int r = ty; r < 32; r += 8) {
        const int k = kb + r;
        t[r][tx] = (k < K) ? src[(size_t)k * LAT + mb + tx] : 0.f;
    }
    __syncthreads();
#pragma unroll
    for (int r = ty; r < 32; r += 8)
        dst[(size_t)(mb + r) * K1PAD + kb + tx] = __float2half_rn(t[tx][r]);
}

__global__ void x_half_kernel(const float* __restrict__ x, int n2)
{
    const int i = blockIdx.x * blockDim.x + threadIdx.x;
    if (i < n2) {
        const float2 v = ((const float2*)x)[i];
        ((__half2*)g_x)[i] = __floats2half2_rn(v.x, v.y);
    }
}

// ---------------------------------------------------------------------------
// GEMM mainloop: 128x128 CTA tile, 512 threads = 16 warps (4m x 4n, warp tile
// 32x32), K-chunks of 32 (2 k16-steps), 5-stage cp.async pipeline (prefetch 4).
// acc[mt][nj][4]: mt in 0..1 (m16), nj in 0..3 (n8).
// ---------------------------------------------------------------------------
__device__ __forceinline__ void gemm_main(
    const __half* __restrict__ A, const __half* __restrict__ B,
    int arow0, int brow0, int ldk, int nchunks,
    char* smem, float acc[2][4][4])
{
    const int tid = threadIdx.x;
    const int lane = tid & 31;
    const int w = tid >> 5;
    const int wm = w >> 2;            // 0..3 (m offset 32 each)
    const int wn = w & 3;             // 0..3 (n offset 32 each)
    const uint32_t sbase = smem_u32(smem);

#pragma unroll
    for (int mt = 0; mt < 2; mt++)
#pragma unroll
        for (int nj = 0; nj < 4; nj++)
#pragma unroll
            for (int q = 0; q < 4; q++) acc[mt][nj][q] = 0.f;

    // loader: 4 threads/row x 128 rows, 16B each; per stage 1 cp.async per tile
    const int lr = tid >> 2;              // 0..127
    const int lcB = (tid & 3) * 16;       // byte offset in 64B row
    const __half* gA = A + (size_t)(arow0 + lr) * ldk + (lcB >> 1);
    const __half* gB = B + (size_t)(brow0 + lr) * ldk + (lcB >> 1);
    const uint32_t adst = sbase + lr * ROWB + lcB;
    const uint32_t bdst = sbase + TILE_B + lr * ROWB + lcB;

    // ldmatrix lane offsets (within a stage)
    uint32_t aoff[2][2], boff[2][2];
#pragma unroll
    for (int ks = 0; ks < 2; ks++) {
#pragma unroll
        for (int mt = 0; mt < 2; mt++)
            aoff[ks][mt] = sbase + (uint32_t)((wm * 32 + mt * 16 + (lane & 15)) * ROWB
                                              + ks * 32 + (lane >> 4) * 16);
#pragma unroll
        for (int nt = 0; nt < 2; nt++)
            boff[ks][nt] = sbase + (uint32_t)(TILE_B
                              + (wn * 32 + nt * 16 + (lane & 7) + (lane >> 4) * 8) * ROWB
                              + ks * 32 + ((lane >> 3) & 1) * 16);
    }

#define LOAD_STAGE(c, s)                                                       \
    do {                                                                       \
        const char* pa = (const char*)(gA + (size_t)(c) * 32);                 \
        const char* pb = (const char*)(gB + (size_t)(c) * 32);                 \
        const uint32_t so_ = (uint32_t)(s) * STAGE_B;                          \
        cpasync16(adst + so_, pa);                                             \
        cpasync16(bdst + so_, pb);                                             \
    } while (0)

#pragma unroll
    for (int c = 0; c < NSTAGE - 1; c++) { LOAD_STAGE(c, c); CP_COMMIT(); }

    int s = 0, ps = NSTAGE - 1;
    for (int c = 0; c < nchunks; ++c) {
        CP_WAIT3();
        __syncthreads();
        if (c + NSTAGE - 1 < nchunks) LOAD_STAGE(c + NSTAGE - 1, ps);
        CP_COMMIT();

        const uint32_t so = (uint32_t)s * STAGE_B;
        uint32_t a[2][2][4], b[2][2][4];
#pragma unroll
        for (int ks = 0; ks < 2; ks++) {
            ldsm4(a[ks][0], aoff[ks][0] + so);
            ldsm4(a[ks][1], aoff[ks][1] + so);
            ldsm4(b[ks][0], boff[ks][0] + so);
            ldsm4(b[ks][1], boff[ks][1] + so);
        }
#pragma unroll
        for (int ks = 0; ks < 2; ks++)
#pragma unroll
            for (int mt = 0; mt < 2; mt++)
#pragma unroll
                for (int nt = 0; nt < 2; nt++) {
                    mma16816(acc[mt][nt * 2 + 0], a[ks][mt], &b[ks][nt][0]);
                    mma16816(acc[mt][nt * 2 + 1], a[ks][mt], &b[ks][nt][2]);
                }
        if (++s == NSTAGE) s = 0;
        if (++ps == NSTAGE) ps = 0;
    }
#undef LOAD_STAGE
}

// ---------------------------------------------------------------------------
// GEMM1: Mt[n][m] = sum_k Ct[n][k] * Wt[m][k]; epilogue rounds to fp16.
// ---------------------------------------------------------------------------
__global__ __launch_bounds__(512, 1) void gemm1_tc()
{
    extern __shared__ __align__(128) char smem[];
    float acc[2][4][4];
    gemm_main(g_Ct, g_Wt, blockIdx.y * 128, blockIdx.x * 128, K1PAD, K1PAD / 32,
              smem, acc);

    const int lane = threadIdx.x & 31;
    const int w = threadIdx.x >> 5;
    const int r0 = blockIdx.y * 128 + (w >> 2) * 32;
    const int c0 = blockIdx.x * 128 + (w & 3) * 32;

#pragma unroll
    for (int mt = 0; mt < 2; mt++) {
#pragma unroll
        for (int nj = 0; nj < 4; nj++) {
            const int col = c0 + nj * 8 + (lane & 3) * 2;
            const float* cc = acc[mt][nj];
#pragma unroll
            for (int h = 0; h < 2; h++) {
                const int r = r0 + mt * 16 + (lane >> 2) + h * 8;
                *(__half2*)(g_Mt + (size_t)r * LAT + col) =
                    __floats2half2_rn(cc[2 * h + 0], cc[2 * h + 1]);
            }
        }
    }
}

// ---------------------------------------------------------------------------
// GEMM2: out[b][n] = sum_m x[b][m] * Mt[n][m]; fused global max.
// ---------------------------------------------------------------------------
__global__ __launch_bounds__(512, 1) void gemm2_tc(float* __restrict__ out)
{
    extern __shared__ __align__(128) char smem[];
    float acc[2][4][4];
    gemm_main(g_x, g_Mt, blockIdx.y * 128, blockIdx.x * 128, LAT, LAT / 32,
              smem, acc);

    const int lane = threadIdx.x & 31;
    const int w = threadIdx.x >> 5;
    const int r0 = blockIdx.y * 128 + (w >> 2) * 32;
    const int c0 = blockIdx.x * 128 + (w & 3) * 32;

    float lmax = -3.402823466e+38f;
#pragma unroll
    for (int mt = 0; mt < 2; mt++) {
#pragma unroll
        for (int nj = 0; nj < 4; nj++) {
            const int col = c0 + nj * 8 + (lane & 3) * 2;
            const float* cc = acc[mt][nj];
#pragma unroll
            for (int h = 0; h < 2; h++) {
                const int r = r0 + mt * 16 + (lane >> 2) + h * 8;
                float2 v = make_float2(cc[2 * h + 0], cc[2 * h + 1]);
                lmax = fmaxf(lmax, fmaxf(v.x, v.y));
                *(float2*)(out + (size_t)r * LAT + col) = v;
            }
        }
    }

#pragma unroll
    for (int o = 16; o > 0; o >>= 1)
        lmax = fmaxf(lmax, __shfl_xor_sync(0xFFFFFFFFu, lmax, o));
    __shared__ float wmax[16];
    if (lane == 0) wmax[w] = lmax;
    __syncthreads();
    if (threadIdx.x == 0) {
        float m = wmax[0];
#pragma unroll
        for (int i = 1; i < 16; i++) m = fmaxf(m, wmax[i]);
        atomicMax(&g_max_bits, fenc(m));
    }
}

// ---------------------------------------------------------------------------
// out *= 1/max
// ---------------------------------------------------------------------------
__global__ void scale_kernel(float* __restrict__ out, int n4)
{
    const float inv = 1.0f / fdec(g_max_bits);
    const int i = blockIdx.x * blockDim.x + threadIdx.x;
    if (i < n4) {
        float4 v = ((float4*)out)[i];
        v.x *= inv; v.y *= inv; v.z *= inv; v.w *= inv;
        ((float4*)out)[i] = v;
    }
}

// ---------------------------------------------------------------------------
extern "C" void kernel_launch(void* const* d_in, const int* in_sizes, int n_in,
                              void* d_out, int out_size)
{
    const float* x = (const float*)d_in[0];   // (B, 2048)
    const float* W = (const float*)d_in[1];   // (NF, 2048)
    const float* C = (const float*)d_in[2];   // (NF, 2048)
    float* out = (float*)d_out;

    const int B  = in_sizes[0] / LAT;         // 4096
    const int NF = in_sizes[1] / LAT;         // 2074

    cudaFuncSetAttribute(gemm1_tc, cudaFuncAttributeMaxDynamicSharedMemorySize, SMEM_BYTES);
    cudaFuncSetAttribute(gemm2_tc, cudaFuncAttributeMaxDynamicSharedMemorySize, SMEM_BYTES);

    dim3 tb(32, 8);
    transpose_half_kernel<<<dim3(LAT / 32, K1PAD / 32), tb>>>(W, NF, 0);
    transpose_half_kernel<<<dim3(LAT / 32, K1PAD / 32), tb>>>(C, NF, 1);
    const int n2 = B * LAT / 2;
    x_half_kernel<<<(n2 + 255) / 256, 256>>>(x, n2);

    // GEMM1: Mt = (W^T C)^T — grid 16x16 = 256 CTAs, 512 threads
    gemm1_tc<<<dim3(LAT / 128, LAT / 128), 512, SMEM_BYTES>>>();

    // GEMM2: out = x @ M + fused global max — grid 16x32 = 512 CTAs
    gemm2_tc<<<dim3(LAT / 128, B / 128), 512, SMEM_BYTES>>>(out);

    const int n4 = out_size / 4;
    scale_kernel<<<(n4 + 255) / 256, 256>>>(out, n4);
}